// round 1
// baseline (speedup 1.0000x reference)
#include <cuda_runtime.h>
#include <math.h>

#define N_TOK 32768
#define NB 64
#define NP 512        // tokens per segment
#define D 128         // dim_qk
#define M 256         // features
#define DV 256        // dim_v
#define EPS_PHI 1e-4f
#define EPS_NORM 1e-8f
#define INV_SQRT_M 0.0625f
// 1 / 128^0.25
#define XSCALE 0.29730177875068026f

// ---------------- scratch (static device globals; no allocation) ------------
__device__ float g_Qp[N_TOK * M];        // phi(Q)
__device__ float g_Ku[N_TOK * M];        // U_k, then overwritten with phi(K)
__device__ float g_hk[N_TOK];
__device__ float g_segmax[NB];
__device__ float g_Ksum[NB * M];
__device__ float g_KV[NB * M * DV];
__device__ float g_norm[N_TOK];

// ---------------- helpers ----------------------------------------------------
__device__ __forceinline__ void atomicMaxF(float* addr, float val) {
    int* ia = (int*)addr;
    int old = *ia;
    while (__int_as_float(old) < val) {
        int assumed = old;
        old = atomicCAS(ia, assumed, __float_as_int(val));
        if (old == assumed) break;
    }
}

__global__ void init_segmax_kernel() {
    if (threadIdx.x < NB) g_segmax[threadIdx.x] = -INFINITY;
}

// ---------------- phi projection: U = (X*XSCALE) @ omega --------------------
// Block: 256 threads, 16 rows x 256 feature columns. Each thread owns one
// feature column for all 16 rows.
template <bool IS_Q>
__global__ void phi_kernel(const float* __restrict__ X,
                           const float* __restrict__ omega) {
    __shared__ float xs[16][D];     // scaled input rows
    __shared__ float us[16][M];     // projected tile
    __shared__ float hs[16];
    __shared__ float mxs[16];

    const int tid  = threadIdx.x;
    const int row0 = blockIdx.x * 16;

    // load 16x128 input tile (scaled); 2048 elems / 256 threads = 8 each
#pragma unroll
    for (int i = 0; i < 8; i++) {
        int e = tid + i * 256;
        int r = e >> 7, c = e & 127;
        xs[r][c] = X[(size_t)(row0 + r) * D + c] * XSCALE;
    }
    __syncthreads();

    float acc[16];
#pragma unroll
    for (int r = 0; r < 16; r++) acc[r] = 0.f;

    for (int k = 0; k < D; k++) {
        float w = omega[(size_t)k * M + tid];   // coalesced, L2-resident
#pragma unroll
        for (int r = 0; r < 16; r++) acc[r] += xs[r][k] * w;  // smem broadcast
    }

#pragma unroll
    for (int r = 0; r < 16; r++) us[r][tid] = acc[r];
    __syncthreads();

    // per-row h (= 0.5 * sum(xs^2) since xs is pre-scaled) and per-row max.
    // warp w handles rows 2w and 2w+1.
    const int warp = tid >> 5, lane = tid & 31;
#pragma unroll
    for (int rr = 0; rr < 2; rr++) {
        int r = warp * 2 + rr;
        float hsum = 0.f;
#pragma unroll
        for (int c = lane; c < D; c += 32) { float v = xs[r][c]; hsum += v * v; }
        float mx = -INFINITY;
#pragma unroll
        for (int c = lane; c < M; c += 32) mx = fmaxf(mx, us[r][c]);
#pragma unroll
        for (int o = 16; o > 0; o >>= 1) {
            hsum += __shfl_xor_sync(0xffffffffu, hsum, o);
            mx = fmaxf(mx, __shfl_xor_sync(0xffffffffu, mx, o));
        }
        if (lane == 0) { hs[r] = 0.5f * hsum; mxs[r] = mx; }
    }
    __syncthreads();

    if (IS_Q) {
        // per-row max: finish phi(Q) right here
#pragma unroll
        for (int r = 0; r < 16; r++) {
            g_Qp[(size_t)(row0 + r) * M + tid] =
                (expf(acc[r] - hs[r] - mxs[r]) + EPS_PHI) * INV_SQRT_M;
        }
    } else {
        // segment max needed: store U, h; push block max into segment max
#pragma unroll
        for (int r = 0; r < 16; r++)
            g_Ku[(size_t)(row0 + r) * M + tid] = acc[r];
        if (tid < 16) g_hk[row0 + tid] = hs[tid];
        if (tid == 0) {
            float bm = mxs[0];
#pragma unroll
            for (int r = 1; r < 16; r++) bm = fmaxf(bm, mxs[r]);
            atomicMaxF(&g_segmax[row0 / NP], bm);
        }
    }
}

// ---------------- phi(K) pass 2: elementwise exp with segment max -----------
__global__ void kp_apply_kernel() {
    int idx = blockIdx.x * blockDim.x + threadIdx.x;   // over N_TOK*M
    int row = idx >> 8;                                // /M
    float u  = g_Ku[idx];
    float mx = g_segmax[row / NP];
    g_Ku[idx] = (expf(u - g_hk[row] - mx) + EPS_PHI) * INV_SQRT_M;
}

// ---------------- Ksum per segment ------------------------------------------
__global__ void ksum_kernel() {
    int b = blockIdx.x, c = threadIdx.x;
    const float* base = g_Ku + (size_t)b * NP * M + c;
    float s = 0.f;
    for (int n = 0; n < NP; n++) s += base[(size_t)n * M];
    g_Ksum[b * M + c] = s;
}

// ---------------- norm[i] = Qp[i] . Ksum[seg(i)] + eps ----------------------
__global__ void norm_kernel() {
    int warp = threadIdx.x >> 5, lane = threadIdx.x & 31;
    int row = blockIdx.x * 8 + warp;
    int b = row / NP;
    float s = 0.f;
#pragma unroll
    for (int c = lane; c < M; c += 32)
        s += g_Qp[(size_t)row * M + c] * g_Ksum[b * M + c];
#pragma unroll
    for (int o = 16; o > 0; o >>= 1) s += __shfl_xor_sync(0xffffffffu, s, o);
    if (lane == 0) g_norm[row] = s + EPS_NORM;
}

// ---------------- KV[b] = Kp_b^T @ V_b  (256m x 256v, K=512) ----------------
// 64x64 tile per block, 256 threads, 4x4 micro-tile, BK=32.
__global__ void kv_gemm_kernel(const float* __restrict__ V) {
    __shared__ float As[32][64];   // [k][m]   (Kp, k = token)
    __shared__ float Bs[32][64];   // [k][v]
    const int b  = blockIdx.z;
    const int m0 = blockIdx.x * 64;
    const int v0 = blockIdx.y * 64;
    const int tid = threadIdx.x;
    const int tx = tid & 15, ty = tid >> 4;

    const float* Kp = g_Ku + (size_t)b * NP * M;
    const float* Vb = V   + (size_t)b * NP * DV;

    float c[4][4] = {};
    for (int k0 = 0; k0 < NP; k0 += 32) {
#pragma unroll
        for (int i = 0; i < 8; i++) {
            int e = tid + i * 256;
            int kk = e >> 6, cc = e & 63;
            As[kk][cc] = Kp[(size_t)(k0 + kk) * M  + m0 + cc];
            Bs[kk][cc] = Vb[(size_t)(k0 + kk) * DV + v0 + cc];
        }
        __syncthreads();
#pragma unroll
        for (int k = 0; k < 32; k++) {
            float a0[4], b0[4];
#pragma unroll
            for (int i = 0; i < 4; i++) a0[i] = As[k][ty * 4 + i];
#pragma unroll
            for (int j = 0; j < 4; j++) b0[j] = Bs[k][tx * 4 + j];
#pragma unroll
            for (int i = 0; i < 4; i++)
#pragma unroll
                for (int j = 0; j < 4; j++) c[i][j] += a0[i] * b0[j];
        }
        __syncthreads();
    }
    float* out = g_KV + ((size_t)b * M + m0) * DV + v0;
#pragma unroll
    for (int i = 0; i < 4; i++)
#pragma unroll
        for (int j = 0; j < 4; j++)
            out[(size_t)(ty * 4 + i) * DV + tx * 4 + j] = c[i][j];
}

// ---------------- out = (Qp_b @ KV[b]) / norm  -------------------------------
// 64 rows x 64 v-cols per block, K=M=256, BK=32.
__global__ void out_gemm_kernel(float* __restrict__ out) {
    __shared__ float As[32][65];   // [k(m)][row], padded against conflicts
    __shared__ float Bs[32][64];   // [k(m)][v]
    const int b  = blockIdx.z;
    const int r0 = blockIdx.x * 64;   // row within segment (0..511)
    const int v0 = blockIdx.y * 64;
    const int tid = threadIdx.x;
    const int tx = tid & 15, ty = tid >> 4;

    const float* Qp = g_Qp + (size_t)b * NP * M;
    const float* KV = g_KV + (size_t)b * M * DV;

    float c[4][4] = {};
    for (int k0 = 0; k0 < M; k0 += 32) {
#pragma unroll
        for (int i = 0; i < 8; i++) {
            int e = tid + i * 256;
            // A: 64 rows x 32 k; coalesce along k (m-dim of Qp)
            int kk = e & 31, rr = e >> 5;
            As[kk][rr] = Qp[(size_t)(r0 + rr) * M + k0 + kk];
            // B: 32 k x 64 v; coalesce along v
            int kb = e >> 6, cv = e & 63;
            Bs[kb][cv] = KV[(size_t)(k0 + kb) * DV + v0 + cv];
        }
        __syncthreads();
#pragma unroll
        for (int k = 0; k < 32; k++) {
            float a0[4], b0[4];
#pragma unroll
            for (int i = 0; i < 4; i++) a0[i] = As[k][ty * 4 + i];
#pragma unroll
            for (int j = 0; j < 4; j++) b0[j] = Bs[k][tx * 4 + j];
#pragma unroll
            for (int i = 0; i < 4; i++)
#pragma unroll
                for (int j = 0; j < 4; j++) c[i][j] += a0[i] * b0[j];
        }
        __syncthreads();
    }
#pragma unroll
    for (int i = 0; i < 4; i++) {
        int grow = b * NP + r0 + ty * 4 + i;
        float inv = 1.0f / g_norm[grow];
#pragma unroll
        for (int j = 0; j < 4; j++)
            out[(size_t)grow * DV + v0 + tx * 4 + j] = c[i][j] * inv;
    }
}

// ---------------- launch ------------------------------------------------------
extern "C" void kernel_launch(void* const* d_in, const int* in_sizes, int n_in,
                              void* d_out, int out_size) {
    const float* Q     = (const float*)d_in[0];
    const float* K     = (const float*)d_in[1];
    const float* V     = (const float*)d_in[2];
    const float* omega = (const float*)d_in[3];
    float* out = (float*)d_out;

    init_segmax_kernel<<<1, 64>>>();
    phi_kernel<true ><<<N_TOK / 16, 256>>>(Q, omega);
    phi_kernel<false><<<N_TOK / 16, 256>>>(K, omega);
    kp_apply_kernel<<<(N_TOK * M) / 256, 256>>>();
    ksum_kernel<<<NB, 256>>>();
    kv_gemm_kernel<<<dim3(4, 4, NB), 256>>>(V);
    norm_kernel<<<N_TOK / 8, 256>>>();
    out_gemm_kernel<<<dim3(8, 4, NB), 256>>>(out);
}

// round 3
// speedup vs baseline: 2.0018x; 2.0018x over previous
#include <cuda_runtime.h>
#include <cuda_fp16.h>
#include <mma.h>
#include <math.h>
#include <stdint.h>

using namespace nvcuda;

#define N_TOK 32768
#define NB 64
#define NP 512
#define D 128
#define M 256
#define DV 256
#define EPS_PHI 1e-4f
#define EPS_NORM 1e-8f
#define INV_SQRT_M 0.0625f
#define XSCALE 0.29730177875068026f   // 1/128^0.25
#define KSCALE 256.0f                 // anti-subnormal scale for Kp (cancels)
#define QSCALE 256.0f                 // anti-subnormal scale for Qp (cancels)

// ---------------- scratch (static device globals) ---------------------------
__device__ float  g_Ku[N_TOK * M];      // U_k pre-exp
__device__ float  g_hk[N_TOK];
__device__ float  g_segmax[NB];
__device__ float  g_Ksum[NB * M];       // scaled
__device__ float  g_norm[N_TOK];        // scaled
__device__ __half g_Qh [N_TOK * M];     // scaled phi(Q), row-major [t][m]
__device__ __half g_Kh [N_TOK * M];     // scaled phi(K), row-major [t][m]
__device__ __half g_Vh [N_TOK * DV];    // V fp16, row-major [t][v]
__device__ __half g_KVh[NB * M * DV];   // scaled KV, row-major [b][m][v]

// ---------------- helpers ----------------------------------------------------
__device__ __forceinline__ void atomicMaxF(float* addr, float val) {
    int* ia = (int*)addr;
    int old = *ia;
    while (__int_as_float(old) < val) {
        int assumed = old;
        old = atomicCAS(ia, assumed, __float_as_int(val));
        if (old == assumed) break;
    }
}

__global__ void init_kernel() {
    g_Ksum[blockIdx.x * 256 + threadIdx.x] = 0.f;
    if (blockIdx.x == 0 && threadIdx.x < NB) g_segmax[threadIdx.x] = -INFINITY;
}

// ---------------- phi projection: U = (X*XSCALE) @ omega --------------------
template <bool IS_Q>
__global__ void phi_kernel(const float* __restrict__ X,
                           const float* __restrict__ omega) {
    __shared__ float xs[16][D];
    __shared__ float us[16][M];
    __shared__ float hs[16];
    __shared__ float mxs[16];

    const int tid  = threadIdx.x;
    const int row0 = blockIdx.x * 16;

#pragma unroll
    for (int i = 0; i < 8; i++) {
        int e = tid + i * 256;
        int r = e >> 7, c = e & 127;
        xs[r][c] = X[(size_t)(row0 + r) * D + c] * XSCALE;
    }
    __syncthreads();

    float acc[16];
#pragma unroll
    for (int r = 0; r < 16; r++) acc[r] = 0.f;

    for (int k = 0; k < D; k += 4) {
        float w0 = omega[(size_t)(k + 0) * M + tid];
        float w1 = omega[(size_t)(k + 1) * M + tid];
        float w2 = omega[(size_t)(k + 2) * M + tid];
        float w3 = omega[(size_t)(k + 3) * M + tid];
#pragma unroll
        for (int r = 0; r < 16; r++) {
            float4 xv = *(const float4*)&xs[r][k];
            acc[r] = fmaf(xv.x, w0, acc[r]);
            acc[r] = fmaf(xv.y, w1, acc[r]);
            acc[r] = fmaf(xv.z, w2, acc[r]);
            acc[r] = fmaf(xv.w, w3, acc[r]);
        }
    }

#pragma unroll
    for (int r = 0; r < 16; r++) us[r][tid] = acc[r];
    __syncthreads();

    const int warp = tid >> 5, lane = tid & 31;
#pragma unroll
    for (int rr = 0; rr < 2; rr++) {
        int r = warp * 2 + rr;
        float hsum = 0.f;
#pragma unroll
        for (int c = lane; c < D; c += 32) { float v = xs[r][c]; hsum += v * v; }
        float mx = -INFINITY;
#pragma unroll
        for (int c = lane; c < M; c += 32) mx = fmaxf(mx, us[r][c]);
#pragma unroll
        for (int o = 16; o > 0; o >>= 1) {
            hsum += __shfl_xor_sync(0xffffffffu, hsum, o);
            mx = fmaxf(mx, __shfl_xor_sync(0xffffffffu, mx, o));
        }
        if (lane == 0) { hs[r] = 0.5f * hsum; mxs[r] = mx; }
    }
    __syncthreads();

    if (IS_Q) {
#pragma unroll
        for (int r = 0; r < 16; r++) {
            float v = (expf(acc[r] - hs[r] - mxs[r]) + EPS_PHI) * (INV_SQRT_M * QSCALE);
            g_Qh[(size_t)(row0 + r) * M + tid] = __float2half_rn(v);
        }
    } else {
#pragma unroll
        for (int r = 0; r < 16; r++)
            g_Ku[(size_t)(row0 + r) * M + tid] = acc[r];
        if (tid < 16) g_hk[row0 + tid] = hs[tid];
        if (tid == 0) {
            float bm = mxs[0];
#pragma unroll
            for (int r = 1; r < 16; r++) bm = fmaxf(bm, mxs[r]);
            atomicMaxF(&g_segmax[row0 / NP], bm);
        }
    }
}

// ---------------- Kp = exp(U-h-segmax) scaled -> fp16 row-major -------------
__global__ void kp_apply_kernel() {
    int i = blockIdx.x * blockDim.x + threadIdx.x;   // over N_TOK*M/2
    int row = i >> 7;
    float2 u = *(const float2*)&g_Ku[(size_t)i * 2];
    float hm = g_hk[row] + g_segmax[row / NP];
    float a = (expf(u.x - hm) + EPS_PHI) * (INV_SQRT_M * KSCALE);
    float b = (expf(u.y - hm) + EPS_PHI) * (INV_SQRT_M * KSCALE);
    *(__half2*)&g_Kh[(size_t)i * 2] = __floats2half2_rn(a, b);
}

// ---------------- V -> fp16 --------------------------------------------------
__global__ void v_half_kernel(const float* __restrict__ V) {
    int i = blockIdx.x * blockDim.x + threadIdx.x;   // over N_TOK*DV/2
    float2 v = *(const float2*)&V[(size_t)i * 2];
    *(__half2*)&g_Vh[(size_t)i * 2] = __floats2half2_rn(v.x, v.y);
}

// ---------------- Ksum (scaled): partial sums + atomicAdd -------------------
__global__ void ksum_kernel() {
    const int b = blockIdx.y, chunk = blockIdx.x, m = threadIdx.x;
    const __half* base = g_Kh + ((size_t)b * NP + chunk * 64) * M + m;
    float s = 0.f;
#pragma unroll
    for (int n = 0; n < 64; n++) s += __half2float(base[(size_t)n * M]);
    atomicAdd(&g_Ksum[b * M + m], s);
}

// ---------------- norm (scaled): Qp . Ksum + eps -----------------------------
__global__ void norm_kernel() {
    const int warp = threadIdx.x >> 5, lane = threadIdx.x & 31;
    const int t = blockIdx.x * 8 + warp;
    const int b = t >> 9;
    float s = 0.f;
#pragma unroll
    for (int j = 0; j < 4; j++) {
        int m = (lane + j * 32) * 2;
        float2 q = __half22float2(*(const __half2*)&g_Qh[(size_t)t * M + m]);
        s += q.x * g_Ksum[b * M + m] + q.y * g_Ksum[b * M + m + 1];
    }
#pragma unroll
    for (int o = 16; o > 0; o >>= 1) s += __shfl_xor_sync(0xffffffffu, s, o);
    if (lane == 0) g_norm[t] = s + EPS_NORM * (KSCALE * QSCALE);
}

// ---------------- GEMM1: KV[b] = Kp^T @ V  (wmma fp16, 128x128 tiles) --------
// A col-major view of Kp [t][m]; B row-major Vh [t][v]; K = 512, BK = 64.
#define LDA1 136
#define SMEM_WMMA 67584   // Cs 128*132*4; overlaps A/B stages

__global__ __launch_bounds__(256) void kv_wmma_kernel() {
    extern __shared__ char smraw[];
    __half* As = (__half*)smraw;                   // [64][136] : [t][m]
    __half* Bs = (__half*)(smraw + 64 * LDA1 * 2); // [64][136] : [t][v]
    float*  Cs = (float*)smraw;                    // [128][132]

    const int b  = blockIdx.z;
    const int m0 = blockIdx.x * 128, v0 = blockIdx.y * 128;
    const int tid = threadIdx.x, warp = tid >> 5;
    const int wr = warp & 1, wc = warp >> 1;       // warp tile: 64(m) x 32(v)

    const __half* Kp = g_Kh + (size_t)b * NP * M;
    const __half* Vh = g_Vh + (size_t)b * NP * DV;

    wmma::fragment<wmma::accumulator, 16, 16, 16, float> c[4][2];
#pragma unroll
    for (int i = 0; i < 4; i++)
#pragma unroll
        for (int j = 0; j < 2; j++) wmma::fill_fragment(c[i][j], 0.f);

    for (int k0 = 0; k0 < NP; k0 += 64) {
        __syncthreads();
#pragma unroll
        for (int i = tid; i < 1024; i += 256) {    // 64 rows x 16 uint4
            int t = i >> 4, q = i & 15;
            ((uint4*)(As + t * LDA1))[q] = ((const uint4*)(Kp + (size_t)(k0 + t) * M  + m0))[q];
            ((uint4*)(Bs + t * LDA1))[q] = ((const uint4*)(Vh + (size_t)(k0 + t) * DV + v0))[q];
        }
        __syncthreads();
#pragma unroll
        for (int kk = 0; kk < 64; kk += 16) {
            wmma::fragment<wmma::matrix_a, 16, 16, 16, __half, wmma::col_major> a[4];
            wmma::fragment<wmma::matrix_b, 16, 16, 16, __half, wmma::row_major> bf[2];
#pragma unroll
            for (int i = 0; i < 4; i++)
                wmma::load_matrix_sync(a[i], As + kk * LDA1 + wr * 64 + i * 16, LDA1);
#pragma unroll
            for (int j = 0; j < 2; j++)
                wmma::load_matrix_sync(bf[j], Bs + kk * LDA1 + wc * 32 + j * 16, LDA1);
#pragma unroll
            for (int i = 0; i < 4; i++)
#pragma unroll
                for (int j = 0; j < 2; j++)
                    wmma::mma_sync(c[i][j], a[i], bf[j], c[i][j]);
        }
    }
    __syncthreads();
#pragma unroll
    for (int i = 0; i < 4; i++)
#pragma unroll
        for (int j = 0; j < 2; j++)
            wmma::store_matrix_sync(Cs + (wr * 64 + i * 16) * 132 + wc * 32 + j * 16,
                                    c[i][j], 132, wmma::mem_row_major);
    __syncthreads();

    __half* KV = g_KVh + (size_t)b * M * DV;
#pragma unroll
    for (int i = tid; i < 8192; i += 256) {        // 128x128 as half2
        int e = i * 2, r = e >> 7, cc = e & 127;
        __half2 h = __floats2half2_rn(Cs[r * 132 + cc], Cs[r * 132 + cc + 1]);
        *(__half2*)(KV + (size_t)(m0 + r) * DV + v0 + cc) = h;
    }
}

// ---------------- GEMM2: out = (Qp @ KV) / norm  (wmma fp16) -----------------
// A row-major Qh [t][m]; B row-major KVh [m][v]; K = 256, BK = 64.
#define LDA2 72
__global__ __launch_bounds__(256) void out_wmma_kernel(float* __restrict__ out) {
    extern __shared__ char smraw[];
    __half* As = (__half*)smraw;                    // [128][72] : [t][k]
    __half* Bs = (__half*)(smraw + 128 * LDA2 * 2); // [64][136] : [k][v]
    float*  Cs = (float*)smraw;                     // [128][132]

    const int b  = blockIdx.z;
    const int t0 = blockIdx.x * 128, v0 = blockIdx.y * 128;
    const int tid = threadIdx.x, warp = tid >> 5;
    const int wr = warp & 1, wc = warp >> 1;

    const __half* Qh = g_Qh  + ((size_t)b * NP + t0) * M;
    const __half* KV = g_KVh + (size_t)b * M * DV;

    wmma::fragment<wmma::accumulator, 16, 16, 16, float> c[4][2];
#pragma unroll
    for (int i = 0; i < 4; i++)
#pragma unroll
        for (int j = 0; j < 2; j++) wmma::fill_fragment(c[i][j], 0.f);

    for (int k0 = 0; k0 < M; k0 += 64) {
        __syncthreads();
#pragma unroll
        for (int i = tid; i < 1024; i += 256) {     // A: 128 rows x 8 uint4
            int r = i >> 3, q = i & 7;
            ((uint4*)(As + r * LDA2))[q] = ((const uint4*)(Qh + (size_t)r * M + k0))[q];
        }
#pragma unroll
        for (int i = tid; i < 1024; i += 256) {     // B: 64 rows x 16 uint4
            int t = i >> 4, q = i & 15;
            ((uint4*)(Bs + t * LDA1))[q] = ((const uint4*)(KV + (size_t)(k0 + t) * DV + v0))[q];
        }
        __syncthreads();
#pragma unroll
        for (int kk = 0; kk < 64; kk += 16) {
            wmma::fragment<wmma::matrix_a, 16, 16, 16, __half, wmma::row_major> a[4];
            wmma::fragment<wmma::matrix_b, 16, 16, 16, __half, wmma::row_major> bf[2];
#pragma unroll
            for (int i = 0; i < 4; i++)
                wmma::load_matrix_sync(a[i], As + (wr * 64 + i * 16) * LDA2 + kk, LDA2);
#pragma unroll
            for (int j = 0; j < 2; j++)
                wmma::load_matrix_sync(bf[j], Bs + kk * LDA1 + wc * 32 + j * 16, LDA1);
#pragma unroll
            for (int i = 0; i < 4; i++)
#pragma unroll
                for (int j = 0; j < 2; j++)
                    wmma::mma_sync(c[i][j], a[i], bf[j], c[i][j]);
        }
    }
    __syncthreads();
#pragma unroll
    for (int i = 0; i < 4; i++)
#pragma unroll
        for (int j = 0; j < 2; j++)
            wmma::store_matrix_sync(Cs + (wr * 64 + i * 16) * 132 + wc * 32 + j * 16,
                                    c[i][j], 132, wmma::mem_row_major);
    __syncthreads();

    float* op = out + ((size_t)b * NP + t0) * DV + v0;
#pragma unroll
    for (int i = tid; i < 8192; i += 256) {         // 128x128 as float2
        int e = i * 2, r = e >> 7, cc = e & 127;
        float inv = 1.0f / g_norm[b * NP + t0 + r];
        float2 v;
        v.x = Cs[r * 132 + cc]     * inv;
        v.y = Cs[r * 132 + cc + 1] * inv;
        *(float2*)(op + (size_t)r * DV + cc) = v;
    }
}

// ---------------- launch ------------------------------------------------------
extern "C" void kernel_launch(void* const* d_in, const int* in_sizes, int n_in,
                              void* d_out, int out_size) {
    const float* Q     = (const float*)d_in[0];
    const float* K     = (const float*)d_in[1];
    const float* V     = (const float*)d_in[2];
    const float* omega = (const float*)d_in[3];
    float* out = (float*)d_out;

    cudaFuncSetAttribute(kv_wmma_kernel,  cudaFuncAttributeMaxDynamicSharedMemorySize, SMEM_WMMA);
    cudaFuncSetAttribute(out_wmma_kernel, cudaFuncAttributeMaxDynamicSharedMemorySize, SMEM_WMMA);

    init_kernel<<<64, 256>>>();
    phi_kernel<true ><<<N_TOK / 16, 256>>>(Q, omega);
    phi_kernel<false><<<N_TOK / 16, 256>>>(K, omega);
    kp_apply_kernel<<<(N_TOK * M / 2) / 256, 256>>>();
    v_half_kernel<<<(N_TOK * DV / 2) / 256, 256>>>(V);
    ksum_kernel<<<dim3(8, NB), 256>>>();
    norm_kernel<<<N_TOK / 8, 256>>>();
    kv_wmma_kernel<<<dim3(2, 2, NB), 256, SMEM_WMMA>>>();
    out_wmma_kernel<<<dim3(4, 2, NB), 256, SMEM_WMMA>>>(out);
}

// round 4
// speedup vs baseline: 3.2481x; 1.6226x over previous
#include <cuda_runtime.h>
#include <cuda_fp16.h>
#include <mma.h>
#include <math.h>
#include <stdint.h>

using namespace nvcuda;

#define N_TOK 32768
#define NB 64
#define NP 512
#define D 128
#define M 256
#define DV 256
#define EPS_PHI 1e-4f
#define EPS_NORM 1e-8f
#define INV_SQRT_M 0.0625f
#define XSCALE 0.29730177875068026f   // 1/128^0.25
#define KSCALE 256.0f                 // anti-subnormal scale for Kp (cancels)
#define QSCALE 256.0f                 // anti-subnormal scale for Qp (cancels)

// ---------------- scratch (static device globals) ---------------------------
__device__ float  g_Ku[N_TOK * M];      // U_k pre-exp
__device__ float  g_hk[N_TOK];
__device__ float  g_segmax[NB];
__device__ float  g_Ksum[NB * M];       // scaled
__device__ float  g_norm[N_TOK];        // scaled
__device__ __half g_Qh [N_TOK * M];     // scaled phi(Q), row-major [t][m]
__device__ __half g_Kh [N_TOK * M];     // scaled phi(K), row-major [t][m]
__device__ __half g_KVh[NB * M * DV];   // scaled KV, row-major [b][m][v]

// ---------------- helpers ----------------------------------------------------
__device__ __forceinline__ void atomicMaxF(float* addr, float val) {
    int* ia = (int*)addr;
    int old = *ia;
    while (__int_as_float(old) < val) {
        int assumed = old;
        old = atomicCAS(ia, assumed, __float_as_int(val));
        if (old == assumed) break;
    }
}

__global__ void init_kernel() {
    g_Ksum[blockIdx.x * 256 + threadIdx.x] = 0.f;
    if (blockIdx.x == 0 && threadIdx.x < NB) g_segmax[threadIdx.x] = -INFINITY;
}

// ---------------- phi via split-fp16 wmma ------------------------------------
// One block: 128 tokens x 256 features, K = 128. U = Xhi@Whi + Xlo@Whi + Xhi@Wlo.
// smem layout (bytes):
//   Ahi 0       [128][136] fp16 (34816)
//   Alo 34816
//   Bhi 69632   [128][264] fp16 (67584)
//   Blo 137216
//   hsm 204800  [128] f32
//   mxs 205312  [128] f32
// Cs overlays Ahi.. : [128][260] f32 (133120)
#define PHI_LDA 136
#define PHI_LDB 264
#define PHI_LDC 260
#define PHI_SMEM 205824

__global__ __launch_bounds__(512, 1) void phi_wmma_kernel(
    const float* __restrict__ Q, const float* __restrict__ K,
    const float* __restrict__ omega) {
    extern __shared__ char smraw[];
    __half* Ahi = (__half*)smraw;
    __half* Alo = (__half*)(smraw + 34816);
    __half* Bhi = (__half*)(smraw + 69632);
    __half* Blo = (__half*)(smraw + 137216);
    float*  Cs  = (float*)smraw;
    float*  hsm = (float*)(smraw + 204800);
    float*  mxs = (float*)(smraw + 205312);

    const int tid  = threadIdx.x;
    const int warp = tid >> 5, lane = tid & 31;
    const bool isq = blockIdx.x < (N_TOK / 128);
    const int tile = isq ? blockIdx.x : blockIdx.x - (N_TOK / 128);
    const int row0 = tile * 128;
    const float* X = isq ? Q : K;

    // ---- load X (scaled) -> Ahi/Alo, compute h per row ----
    {
        int r = tid >> 2, j = tid & 3;
        const float4* src = (const float4*)(X + (size_t)(row0 + r) * D + j * 32);
        __half* ah = Ahi + r * PHI_LDA + j * 32;
        __half* al = Alo + r * PHI_LDA + j * 32;
        float ss = 0.f;
#pragma unroll
        for (int q = 0; q < 8; q++) {
            float4 v = src[q];
            v.x *= XSCALE; v.y *= XSCALE; v.z *= XSCALE; v.w *= XSCALE;
            ss += v.x * v.x + v.y * v.y + v.z * v.z + v.w * v.w;
            __half hx = __float2half_rn(v.x), hy = __float2half_rn(v.y);
            __half hz = __float2half_rn(v.z), hw = __float2half_rn(v.w);
            ((__half2*)(ah + q * 4))[0] = __halves2half2(hx, hy);
            ((__half2*)(ah + q * 4))[1] = __halves2half2(hz, hw);
            ((__half2*)(al + q * 4))[0] = __floats2half2_rn(v.x - __half2float(hx),
                                                            v.y - __half2float(hy));
            ((__half2*)(al + q * 4))[1] = __floats2half2_rn(v.z - __half2float(hz),
                                                            v.w - __half2float(hw));
        }
        ss += __shfl_xor_sync(0xffffffffu, ss, 1);
        ss += __shfl_xor_sync(0xffffffffu, ss, 2);
        if (j == 0) hsm[r] = 0.5f * ss;
    }
    // ---- load omega -> Bhi/Blo ----
#pragma unroll
    for (int it = 0; it < 16; it++) {
        int i = it * 512 + tid;          // 8192 float4
        int rr = i >> 6, c4 = i & 63;
        float4 v = ((const float4*)omega)[i];
        __half* bh = Bhi + rr * PHI_LDB + c4 * 4;
        __half* bl = Blo + rr * PHI_LDB + c4 * 4;
        __half hx = __float2half_rn(v.x), hy = __float2half_rn(v.y);
        __half hz = __float2half_rn(v.z), hw = __float2half_rn(v.w);
        ((__half2*)bh)[0] = __halves2half2(hx, hy);
        ((__half2*)bh)[1] = __halves2half2(hz, hw);
        ((__half2*)bl)[0] = __floats2half2_rn(v.x - __half2float(hx),
                                              v.y - __half2float(hy));
        ((__half2*)bl)[1] = __floats2half2_rn(v.z - __half2float(hz),
                                              v.w - __half2float(hw));
    }
    __syncthreads();

    // ---- MMA: warp tile 32 tokens x 64 features ----
    const int wr = warp >> 2, wc = warp & 3;
    wmma::fragment<wmma::accumulator, 16, 16, 16, float> c[2][4];
#pragma unroll
    for (int i = 0; i < 2; i++)
#pragma unroll
        for (int j = 0; j < 4; j++) wmma::fill_fragment(c[i][j], 0.f);

#pragma unroll
    for (int ks = 0; ks < 8; ks++) {
        int kk = ks * 16;
        wmma::fragment<wmma::matrix_a, 16, 16, 16, __half, wmma::row_major> ah[2], al[2];
        wmma::fragment<wmma::matrix_b, 16, 16, 16, __half, wmma::row_major> bh[4], bl[4];
#pragma unroll
        for (int i = 0; i < 2; i++) {
            wmma::load_matrix_sync(ah[i], Ahi + (wr * 32 + i * 16) * PHI_LDA + kk, PHI_LDA);
            wmma::load_matrix_sync(al[i], Alo + (wr * 32 + i * 16) * PHI_LDA + kk, PHI_LDA);
        }
#pragma unroll
        for (int j = 0; j < 4; j++) {
            wmma::load_matrix_sync(bh[j], Bhi + kk * PHI_LDB + wc * 64 + j * 16, PHI_LDB);
            wmma::load_matrix_sync(bl[j], Blo + kk * PHI_LDB + wc * 64 + j * 16, PHI_LDB);
        }
#pragma unroll
        for (int i = 0; i < 2; i++)
#pragma unroll
            for (int j = 0; j < 4; j++) {
                wmma::mma_sync(c[i][j], ah[i], bh[j], c[i][j]);
                wmma::mma_sync(c[i][j], al[i], bh[j], c[i][j]);
                wmma::mma_sync(c[i][j], ah[i], bl[j], c[i][j]);
            }
    }
    __syncthreads();

    if (isq) {
        // stage to Cs, per-row max, exp, write fp16
#pragma unroll
        for (int i = 0; i < 2; i++)
#pragma unroll
            for (int j = 0; j < 4; j++)
                wmma::store_matrix_sync(Cs + (wr * 32 + i * 16) * PHI_LDC + wc * 64 + j * 16,
                                        c[i][j], PHI_LDC, wmma::mem_row_major);
        __syncthreads();
#pragma unroll
        for (int rr = 0; rr < 8; rr++) {
            int row = warp * 8 + rr;
            float mx = -INFINITY;
#pragma unroll
            for (int cc = lane; cc < M; cc += 32) mx = fmaxf(mx, Cs[row * PHI_LDC + cc]);
#pragma unroll
            for (int o = 16; o > 0; o >>= 1) mx = fmaxf(mx, __shfl_xor_sync(0xffffffffu, mx, o));
            if (lane == 0) mxs[row] = mx;
        }
        __syncthreads();
#pragma unroll
        for (int it = 0; it < 32; it++) {
            int i = it * 512 + tid;      // 16384 half2 outputs
            int row = i >> 7, c2 = i & 127;
            float hm = hsm[row] + mxs[row];
            float2 u = *(const float2*)&Cs[row * PHI_LDC + c2 * 2];
            float a = (__expf(u.x - hm) + EPS_PHI) * (INV_SQRT_M * QSCALE);
            float b = (__expf(u.y - hm) + EPS_PHI) * (INV_SQRT_M * QSCALE);
            ((__half2*)g_Qh)[(size_t)(row0 + row) * (M / 2) + c2] = __floats2half2_rn(a, b);
        }
    } else {
        // block max from fragments -> segment atomicMax; U straight to gmem
        float bm = -INFINITY;
#pragma unroll
        for (int i = 0; i < 2; i++)
#pragma unroll
            for (int j = 0; j < 4; j++)
#pragma unroll
                for (int e = 0; e < c[i][j].num_elements; e++)
                    bm = fmaxf(bm, c[i][j].x[e]);
#pragma unroll
        for (int o = 16; o > 0; o >>= 1) bm = fmaxf(bm, __shfl_xor_sync(0xffffffffu, bm, o));
        if (lane == 0) mxs[warp] = bm;
        float* Udst = g_Ku + (size_t)row0 * M;
#pragma unroll
        for (int i = 0; i < 2; i++)
#pragma unroll
            for (int j = 0; j < 4; j++)
                wmma::store_matrix_sync(Udst + (size_t)(wr * 32 + i * 16) * M + wc * 64 + j * 16,
                                        c[i][j], M, wmma::mem_row_major);
        if (tid < 128) g_hk[row0 + tid] = hsm[tid];
        __syncthreads();
        if (tid == 0) {
            float m0 = mxs[0];
#pragma unroll
            for (int w = 1; w < 16; w++) m0 = fmaxf(m0, mxs[w]);
            atomicMaxF(&g_segmax[row0 / NP], m0);
        }
    }
}

// ---------------- Kp = exp(U-h-segmax) scaled -> fp16 row-major -------------
__global__ void kp_apply_kernel() {
    int i = blockIdx.x * blockDim.x + threadIdx.x;   // over N_TOK*M/2
    int row = i >> 7;
    float2 u = *(const float2*)&g_Ku[(size_t)i * 2];
    float hm = g_hk[row] + g_segmax[row / NP];
    float a = (__expf(u.x - hm) + EPS_PHI) * (INV_SQRT_M * KSCALE);
    float b = (__expf(u.y - hm) + EPS_PHI) * (INV_SQRT_M * KSCALE);
    *(__half2*)&g_Kh[(size_t)i * 2] = __floats2half2_rn(a, b);
}

// ---------------- Ksum (scaled): partial sums + atomicAdd -------------------
__global__ void ksum_kernel() {
    const int b = blockIdx.y, chunk = blockIdx.x, m = threadIdx.x;
    const __half* base = g_Kh + ((size_t)b * NP + chunk * 64) * M + m;
    float s = 0.f;
#pragma unroll
    for (int n = 0; n < 64; n++) s += __half2float(base[(size_t)n * M]);
    atomicAdd(&g_Ksum[b * M + m], s);
}

// ---------------- norm (scaled): Qp . Ksum + eps -----------------------------
__global__ void norm_kernel() {
    const int warp = threadIdx.x >> 5, lane = threadIdx.x & 31;
    const int t = blockIdx.x * 8 + warp;
    const int b = t >> 9;
    float s = 0.f;
#pragma unroll
    for (int j = 0; j < 4; j++) {
        int m = (lane + j * 32) * 2;
        float2 q = __half22float2(*(const __half2*)&g_Qh[(size_t)t * M + m]);
        s += q.x * g_Ksum[b * M + m] + q.y * g_Ksum[b * M + m + 1];
    }
#pragma unroll
    for (int o = 16; o > 0; o >>= 1) s += __shfl_xor_sync(0xffffffffu, s, o);
    if (lane == 0) g_norm[t] = s + EPS_NORM * (KSCALE * QSCALE);
}

// ---------------- GEMM1: KV[b] = Kp^T @ V  (wmma fp16, 128x128 tiles) --------
#define LDA1 136
#define SMEM_WMMA 67584

__global__ __launch_bounds__(256) void kv_wmma_kernel(const float* __restrict__ V) {
    extern __shared__ char smraw[];
    __half* As = (__half*)smraw;                   // [64][136] : [t][m]
    __half* Bs = (__half*)(smraw + 64 * LDA1 * 2); // [64][136] : [t][v]
    float*  Cs = (float*)smraw;                    // [128][132]

    const int b  = blockIdx.z;
    const int m0 = blockIdx.x * 128, v0 = blockIdx.y * 128;
    const int tid = threadIdx.x, warp = tid >> 5;
    const int wr = warp & 1, wc = warp >> 1;

    const __half* Kp = g_Kh + (size_t)b * NP * M;
    const float*  Vb = V    + (size_t)b * NP * DV;

    wmma::fragment<wmma::accumulator, 16, 16, 16, float> c[4][2];
#pragma unroll
    for (int i = 0; i < 4; i++)
#pragma unroll
        for (int j = 0; j < 2; j++) wmma::fill_fragment(c[i][j], 0.f);

    for (int k0 = 0; k0 < NP; k0 += 64) {
        __syncthreads();
#pragma unroll
        for (int i = tid; i < 1024; i += 256) {    // A: 64 rows x 16 uint4 (fp16)
            int t = i >> 4, q = i & 15;
            ((uint4*)(As + t * LDA1))[q] = ((const uint4*)(Kp + (size_t)(k0 + t) * M + m0))[q];
        }
#pragma unroll
        for (int i = tid; i < 2048; i += 256) {    // B: 64 rows x 32 float4 -> fp16
            int t = i >> 5, q = i & 31;
            float4 f = ((const float4*)(Vb + (size_t)(k0 + t) * DV + v0))[q];
            ((__half2*)(Bs + t * LDA1))[q * 2]     = __floats2half2_rn(f.x, f.y);
            ((__half2*)(Bs + t * LDA1))[q * 2 + 1] = __floats2half2_rn(f.z, f.w);
        }
        __syncthreads();
#pragma unroll
        for (int kk = 0; kk < 64; kk += 16) {
            wmma::fragment<wmma::matrix_a, 16, 16, 16, __half, wmma::col_major> a[4];
            wmma::fragment<wmma::matrix_b, 16, 16, 16, __half, wmma::row_major> bf[2];
#pragma unroll
            for (int i = 0; i < 4; i++)
                wmma::load_matrix_sync(a[i], As + kk * LDA1 + wr * 64 + i * 16, LDA1);
#pragma unroll
            for (int j = 0; j < 2; j++)
                wmma::load_matrix_sync(bf[j], Bs + kk * LDA1 + wc * 32 + j * 16, LDA1);
#pragma unroll
            for (int i = 0; i < 4; i++)
#pragma unroll
                for (int j = 0; j < 2; j++)
                    wmma::mma_sync(c[i][j], a[i], bf[j], c[i][j]);
        }
    }
    __syncthreads();
#pragma unroll
    for (int i = 0; i < 4; i++)
#pragma unroll
        for (int j = 0; j < 2; j++)
            wmma::store_matrix_sync(Cs + (wr * 64 + i * 16) * 132 + wc * 32 + j * 16,
                                    c[i][j], 132, wmma::mem_row_major);
    __syncthreads();

    __half* KV = g_KVh + (size_t)b * M * DV;
#pragma unroll
    for (int i = tid; i < 8192; i += 256) {
        int e = i * 2, r = e >> 7, cc = e & 127;
        __half2 h = __floats2half2_rn(Cs[r * 132 + cc], Cs[r * 132 + cc + 1]);
        *(__half2*)(KV + (size_t)(m0 + r) * DV + v0 + cc) = h;
    }
}

// ---------------- GEMM2: out = (Qp @ KV) / norm  (wmma fp16) -----------------
#define LDA2 72
__global__ __launch_bounds__(256) void out_wmma_kernel(float* __restrict__ out) {
    extern __shared__ char smraw[];
    __half* As = (__half*)smraw;                    // [128][72] : [t][k]
    __half* Bs = (__half*)(smraw + 128 * LDA2 * 2); // [64][136] : [k][v]
    float*  Cs = (float*)smraw;                     // [128][132]

    const int b  = blockIdx.z;
    const int t0 = blockIdx.x * 128, v0 = blockIdx.y * 128;
    const int tid = threadIdx.x, warp = tid >> 5;
    const int wr = warp & 1, wc = warp >> 1;

    const __half* Qh = g_Qh  + ((size_t)b * NP + t0) * M;
    const __half* KV = g_KVh + (size_t)b * M * DV;

    wmma::fragment<wmma::accumulator, 16, 16, 16, float> c[4][2];
#pragma unroll
    for (int i = 0; i < 4; i++)
#pragma unroll
        for (int j = 0; j < 2; j++) wmma::fill_fragment(c[i][j], 0.f);

    for (int k0 = 0; k0 < M; k0 += 64) {
        __syncthreads();
#pragma unroll
        for (int i = tid; i < 1024; i += 256) {
            int r = i >> 3, q = i & 7;
            ((uint4*)(As + r * LDA2))[q] = ((const uint4*)(Qh + (size_t)r * M + k0))[q];
        }
#pragma unroll
        for (int i = tid; i < 1024; i += 256) {
            int t = i >> 4, q = i & 15;
            ((uint4*)(Bs + t * LDA1))[q] = ((const uint4*)(KV + (size_t)(k0 + t) * DV + v0))[q];
        }
        __syncthreads();
#pragma unroll
        for (int kk = 0; kk < 64; kk += 16) {
            wmma::fragment<wmma::matrix_a, 16, 16, 16, __half, wmma::row_major> a[4];
            wmma::fragment<wmma::matrix_b, 16, 16, 16, __half, wmma::row_major> bf[2];
#pragma unroll
            for (int i = 0; i < 4; i++)
                wmma::load_matrix_sync(a[i], As + (wr * 64 + i * 16) * LDA2 + kk, LDA2);
#pragma unroll
            for (int j = 0; j < 2; j++)
                wmma::load_matrix_sync(bf[j], Bs + kk * LDA1 + wc * 32 + j * 16, LDA1);
#pragma unroll
            for (int i = 0; i < 4; i++)
#pragma unroll
                for (int j = 0; j < 2; j++)
                    wmma::mma_sync(c[i][j], a[i], bf[j], c[i][j]);
        }
    }
    __syncthreads();
#pragma unroll
    for (int i = 0; i < 4; i++)
#pragma unroll
        for (int j = 0; j < 2; j++)
            wmma::store_matrix_sync(Cs + (wr * 64 + i * 16) * 132 + wc * 32 + j * 16,
                                    c[i][j], 132, wmma::mem_row_major);
    __syncthreads();

    float* op = out + ((size_t)b * NP + t0) * DV + v0;
#pragma unroll
    for (int i = tid; i < 8192; i += 256) {
        int e = i * 2, r = e >> 7, cc = e & 127;
        float inv = 1.0f / g_norm[b * NP + t0 + r];
        float2 v;
        v.x = Cs[r * 132 + cc]     * inv;
        v.y = Cs[r * 132 + cc + 1] * inv;
        *(float2*)(op + (size_t)r * DV + cc) = v;
    }
}

// ---------------- launch ------------------------------------------------------
extern "C" void kernel_launch(void* const* d_in, const int* in_sizes, int n_in,
                              void* d_out, int out_size) {
    const float* Q     = (const float*)d_in[0];
    const float* K     = (const float*)d_in[1];
    const float* V     = (const float*)d_in[2];
    const float* omega = (const float*)d_in[3];
    float* out = (float*)d_out;

    cudaFuncSetAttribute(phi_wmma_kernel, cudaFuncAttributeMaxDynamicSharedMemorySize, PHI_SMEM);
    cudaFuncSetAttribute(kv_wmma_kernel,  cudaFuncAttributeMaxDynamicSharedMemorySize, SMEM_WMMA);
    cudaFuncSetAttribute(out_wmma_kernel, cudaFuncAttributeMaxDynamicSharedMemorySize, SMEM_WMMA);

    init_kernel<<<64, 256>>>();
    phi_wmma_kernel<<<2 * (N_TOK / 128), 512, PHI_SMEM>>>(Q, K, omega);
    kp_apply_kernel<<<(N_TOK * M / 2) / 256, 256>>>();
    ksum_kernel<<<dim3(8, NB), 256>>>();
    norm_kernel<<<N_TOK / 8, 256>>>();
    kv_wmma_kernel<<<dim3(2, 2, NB), 256, SMEM_WMMA>>>(V);
    out_wmma_kernel<<<dim3(4, 2, NB), 256, SMEM_WMMA>>>(out);
}

// round 5
// speedup vs baseline: 3.6373x; 1.1198x over previous
#include <cuda_runtime.h>
#include <cuda_fp16.h>
#include <mma.h>
#include <math.h>
#include <stdint.h>

using namespace nvcuda;

#define N_TOK 32768
#define NB 64
#define NP 512
#define D 128
#define M 256
#define DV 256
#define EPS_PHI 1e-4f
#define EPS_NORM 1e-8f
#define INV_SQRT_M 0.0625f
#define XSCALE 0.29730177875068026f   // 1/128^0.25
#define KSCALE 256.0f                 // anti-subnormal scale for Kp (cancels)
#define QSCALE 256.0f                 // anti-subnormal scale for Qp (cancels)
#define ESCALE 512.0f                 // storage scale for raw exp of K

// ---------------- scratch (static device globals) ---------------------------
__device__ float  g_segmax[NB];
__device__ float  g_bmax[N_TOK / 128];   // per-phi-block max (K side)
__device__ float  g_Ksum[NB * M];        // scaled, fp32
__device__ __half g_Qh [N_TOK * M];      // scaled phi(Q), row-major [t][m]
__device__ __half g_Ke [N_TOK * M];      // exp(U-h-bmax)*ESCALE (K side)
__device__ __half g_KVh[NB * M * DV];    // scaled KV, row-major [b][m][v]
__device__ __half g_Whi[D * M];          // omega hi fp16
__device__ __half g_Wlo[D * M];          // omega lo fp16

// ---------------- helpers ----------------------------------------------------
__device__ __forceinline__ void atomicMaxF(float* addr, float val) {
    int* ia = (int*)addr;
    int old = *ia;
    while (__int_as_float(old) < val) {
        int assumed = old;
        old = atomicCAS(ia, assumed, __float_as_int(val));
        if (old == assumed) break;
    }
}

__global__ void init_kernel() {
    if (threadIdx.x < NB) g_segmax[threadIdx.x] = -INFINITY;
}

__global__ void omega_split_kernel(const float* __restrict__ omega) {
    int i = blockIdx.x * 256 + threadIdx.x;     // over D*M = 32768
    float w = omega[i];
    __half hi = __float2half_rn(w);
    g_Whi[i] = hi;
    g_Wlo[i] = __float2half_rn(w - __half2float(hi));
}

// ---------------- phi via split-fp16 wmma ------------------------------------
// One block: 128 tokens x 256 features, K=128. U = Xhi@Whi + Xlo@Whi + Xhi@Wlo.
#define PHI_LDA 136
#define PHI_LDB 264
#define PHI_LDC 260
#define PHI_SMEM 205824

__global__ __launch_bounds__(512, 1) void phi_wmma_kernel(
    const float* __restrict__ Q, const float* __restrict__ K) {
    extern __shared__ char smraw[];
    __half* Ahi = (__half*)smraw;
    __half* Alo = (__half*)(smraw + 34816);
    __half* Bhi = (__half*)(smraw + 69632);
    __half* Blo = (__half*)(smraw + 137216);
    float*  Cs  = (float*)smraw;
    float*  hsm = (float*)(smraw + 204800);
    float*  mxs = (float*)(smraw + 205312);

    const int tid  = threadIdx.x;
    const int warp = tid >> 5, lane = tid & 31;
    const bool isq = blockIdx.x < (N_TOK / 128);
    const int tile = isq ? blockIdx.x : blockIdx.x - (N_TOK / 128);
    const int row0 = tile * 128;
    const float* X = isq ? Q : K;

    // ---- load X (scaled) -> Ahi/Alo, compute h per row ----
    {
        int r = tid >> 2, j = tid & 3;
        const float4* src = (const float4*)(X + (size_t)(row0 + r) * D + j * 32);
        __half* ah = Ahi + r * PHI_LDA + j * 32;
        __half* al = Alo + r * PHI_LDA + j * 32;
        float ss = 0.f;
#pragma unroll
        for (int q = 0; q < 8; q++) {
            float4 v = src[q];
            v.x *= XSCALE; v.y *= XSCALE; v.z *= XSCALE; v.w *= XSCALE;
            ss += v.x * v.x + v.y * v.y + v.z * v.z + v.w * v.w;
            __half hx = __float2half_rn(v.x), hy = __float2half_rn(v.y);
            __half hz = __float2half_rn(v.z), hw = __float2half_rn(v.w);
            ((__half2*)(ah + q * 4))[0] = __halves2half2(hx, hy);
            ((__half2*)(ah + q * 4))[1] = __halves2half2(hz, hw);
            ((__half2*)(al + q * 4))[0] = __floats2half2_rn(v.x - __half2float(hx),
                                                            v.y - __half2float(hy));
            ((__half2*)(al + q * 4))[1] = __floats2half2_rn(v.z - __half2float(hz),
                                                            v.w - __half2float(hw));
        }
        ss += __shfl_xor_sync(0xffffffffu, ss, 1);
        ss += __shfl_xor_sync(0xffffffffu, ss, 2);
        if (j == 0) hsm[r] = 0.5f * ss;
    }
    // ---- copy pre-split omega -> Bhi/Blo ----
#pragma unroll
    for (int it = 0; it < 16; it++) {
        int i = it * 512 + tid;           // 8192 uint4 total
        int sel = i >> 12;                // 0: hi, 1: lo
        int j = i & 4095;
        int rr = j >> 5, c8 = j & 31;
        uint4 v = sel ? ((const uint4*)g_Wlo)[j] : ((const uint4*)g_Whi)[j];
        *(uint4*)((sel ? Blo : Bhi) + rr * PHI_LDB + c8 * 8) = v;
    }
    __syncthreads();

    // ---- MMA: warp tile 32 tokens x 64 features ----
    const int wr = warp >> 2, wc = warp & 3;
    wmma::fragment<wmma::accumulator, 16, 16, 16, float> c[2][4];
#pragma unroll
    for (int i = 0; i < 2; i++)
#pragma unroll
        for (int j = 0; j < 4; j++) wmma::fill_fragment(c[i][j], 0.f);

#pragma unroll
    for (int ks = 0; ks < 8; ks++) {
        int kk = ks * 16;
        wmma::fragment<wmma::matrix_a, 16, 16, 16, __half, wmma::row_major> ah[2], al[2];
        wmma::fragment<wmma::matrix_b, 16, 16, 16, __half, wmma::row_major> bh[4], bl[4];
#pragma unroll
        for (int i = 0; i < 2; i++) {
            wmma::load_matrix_sync(ah[i], Ahi + (wr * 32 + i * 16) * PHI_LDA + kk, PHI_LDA);
            wmma::load_matrix_sync(al[i], Alo + (wr * 32 + i * 16) * PHI_LDA + kk, PHI_LDA);
        }
#pragma unroll
        for (int j = 0; j < 4; j++) {
            wmma::load_matrix_sync(bh[j], Bhi + kk * PHI_LDB + wc * 64 + j * 16, PHI_LDB);
            wmma::load_matrix_sync(bl[j], Blo + kk * PHI_LDB + wc * 64 + j * 16, PHI_LDB);
        }
#pragma unroll
        for (int i = 0; i < 2; i++)
#pragma unroll
            for (int j = 0; j < 4; j++) {
                wmma::mma_sync(c[i][j], ah[i], bh[j], c[i][j]);
                wmma::mma_sync(c[i][j], al[i], bh[j], c[i][j]);
                wmma::mma_sync(c[i][j], ah[i], bl[j], c[i][j]);
            }
    }
    __syncthreads();

    if (isq) {
#pragma unroll
        for (int i = 0; i < 2; i++)
#pragma unroll
            for (int j = 0; j < 4; j++)
                wmma::store_matrix_sync(Cs + (wr * 32 + i * 16) * PHI_LDC + wc * 64 + j * 16,
                                        c[i][j], PHI_LDC, wmma::mem_row_major);
        __syncthreads();
#pragma unroll
        for (int rr = 0; rr < 8; rr++) {
            int row = warp * 8 + rr;
            float mx = -INFINITY;
#pragma unroll
            for (int cc = lane; cc < M; cc += 32) mx = fmaxf(mx, Cs[row * PHI_LDC + cc]);
#pragma unroll
            for (int o = 16; o > 0; o >>= 1) mx = fmaxf(mx, __shfl_xor_sync(0xffffffffu, mx, o));
            if (lane == 0) mxs[row] = mx;
        }
        __syncthreads();
#pragma unroll
        for (int it = 0; it < 32; it++) {
            int i = it * 512 + tid;
            int row = i >> 7, c2 = i & 127;
            float hm = hsm[row] + mxs[row];
            float2 u = *(const float2*)&Cs[row * PHI_LDC + c2 * 2];
            float a = (__expf(u.x - hm) + EPS_PHI) * (INV_SQRT_M * QSCALE);
            float b = (__expf(u.y - hm) + EPS_PHI) * (INV_SQRT_M * QSCALE);
            ((__half2*)g_Qh)[(size_t)(row0 + row) * (M / 2) + c2] = __floats2half2_rn(a, b);
        }
    } else {
        // block max from fragments
        float bm = -INFINITY;
#pragma unroll
        for (int i = 0; i < 2; i++)
#pragma unroll
            for (int j = 0; j < 4; j++)
#pragma unroll
                for (int e = 0; e < c[i][j].num_elements; e++)
                    bm = fmaxf(bm, c[i][j].x[e]);
#pragma unroll
        for (int o = 16; o > 0; o >>= 1) bm = fmaxf(bm, __shfl_xor_sync(0xffffffffu, bm, o));
        if (lane == 0) mxs[warp] = bm;
        __syncthreads();
#pragma unroll
        for (int i = 0; i < 2; i++)
#pragma unroll
            for (int j = 0; j < 4; j++)
                wmma::store_matrix_sync(Cs + (wr * 32 + i * 16) * PHI_LDC + wc * 64 + j * 16,
                                        c[i][j], PHI_LDC, wmma::mem_row_major);
        float bmax = mxs[0];
#pragma unroll
        for (int w = 1; w < 16; w++) bmax = fmaxf(bmax, mxs[w]);
        __syncthreads();
#pragma unroll
        for (int it = 0; it < 32; it++) {
            int i = it * 512 + tid;
            int row = i >> 7, c2 = i & 127;
            float hm = hsm[row] + bmax;
            float2 u = *(const float2*)&Cs[row * PHI_LDC + c2 * 2];
            float a = __expf(u.x - hm) * ESCALE;
            float b = __expf(u.y - hm) * ESCALE;
            ((__half2*)g_Ke)[(size_t)(row0 + row) * (M / 2) + c2] = __floats2half2_rn(a, b);
        }
        if (tid == 0) {
            g_bmax[tile] = bmax;
            atomicMaxF(&g_segmax[tile >> 2], bmax);
        }
    }
}

// ---------------- GEMM1: KV[b] = Kp^T @ V  (+ fused Ksum) --------------------
#define LDA1 136
#define SMEM1 68608   // As/Bs 34816, Cs overlay 67584, ksbuf @67584 (1024)

__global__ __launch_bounds__(256) void kv_wmma_kernel(const float* __restrict__ V) {
    extern __shared__ char smraw[];
    __half* As = (__half*)smraw;                   // [64][136] : [t][m] corrected Kp
    __half* Bs = (__half*)(smraw + 64 * LDA1 * 2); // [64][136] : [t][v]
    float*  Cs = (float*)smraw;                    // [128][132]
    float*  ksbuf = (float*)(smraw + 67584);       // [256]

    const int b  = blockIdx.z;
    const int m0 = blockIdx.x * 128, v0 = blockIdx.y * 128;
    const int tid = threadIdx.x, warp = tid >> 5;
    const int wr = warp & 1, wc = warp >> 1;

    // per-128-token-chunk correction: (e/ESCALE*corr + EPS)*16 = e*c1 + c2
    const float sgm = g_segmax[b];
    __half2 c1h[4];
#pragma unroll
    for (int cb = 0; cb < 4; cb++) {
        float corr = __expf(g_bmax[b * 4 + cb] - sgm) * (INV_SQRT_M * KSCALE / ESCALE);
        c1h[cb] = __float2half2_rn(corr);
    }
    const __half2 c2h = __float2half2_rn(EPS_PHI * INV_SQRT_M * KSCALE);

    const __half* Ke = g_Ke + (size_t)b * NP * M;
    const float*  Vb = V    + (size_t)b * NP * DV;

    wmma::fragment<wmma::accumulator, 16, 16, 16, float> c[4][2];
#pragma unroll
    for (int i = 0; i < 4; i++)
#pragma unroll
        for (int j = 0; j < 2; j++) wmma::fill_fragment(c[i][j], 0.f);

    float kpart = 0.f;
    for (int k0 = 0; k0 < NP; k0 += 64) {
        __syncthreads();
        __half2 c1 = c1h[k0 >> 7];
#pragma unroll
        for (int i = tid; i < 1024; i += 256) {    // A: 64 rows x 16 uint4
            int t = i >> 4, q = i & 15;
            uint4 raw = ((const uint4*)(Ke + (size_t)(k0 + t) * M + m0))[q];
            __half2* pr = (__half2*)&raw;
            pr[0] = __hfma2(pr[0], c1, c2h);
            pr[1] = __hfma2(pr[1], c1, c2h);
            pr[2] = __hfma2(pr[2], c1, c2h);
            pr[3] = __hfma2(pr[3], c1, c2h);
            ((uint4*)(As + t * LDA1))[q] = raw;
        }
#pragma unroll
        for (int i = tid; i < 2048; i += 256) {    // B: 64 rows x 32 float4 -> fp16
            int t = i >> 5, q = i & 31;
            float4 f = ((const float4*)(Vb + (size_t)(k0 + t) * DV + v0))[q];
            ((__half2*)(Bs + t * LDA1))[q * 2]     = __floats2half2_rn(f.x, f.y);
            ((__half2*)(Bs + t * LDA1))[q * 2 + 1] = __floats2half2_rn(f.z, f.w);
        }
        __syncthreads();
        if (blockIdx.y == 0) {                     // fused Ksum partials
            int m = tid & 127, hf = tid >> 7;
            const __half* col = As + (hf * 32) * LDA1 + m;
#pragma unroll
            for (int tt = 0; tt < 32; tt++) kpart += __half2float(col[tt * LDA1]);
        }
#pragma unroll
        for (int kk = 0; kk < 64; kk += 16) {
            wmma::fragment<wmma::matrix_a, 16, 16, 16, __half, wmma::col_major> a[4];
            wmma::fragment<wmma::matrix_b, 16, 16, 16, __half, wmma::row_major> bf[2];
#pragma unroll
            for (int i = 0; i < 4; i++)
                wmma::load_matrix_sync(a[i], As + kk * LDA1 + wr * 64 + i * 16, LDA1);
#pragma unroll
            for (int j = 0; j < 2; j++)
                wmma::load_matrix_sync(bf[j], Bs + kk * LDA1 + wc * 32 + j * 16, LDA1);
#pragma unroll
            for (int i = 0; i < 4; i++)
#pragma unroll
                for (int j = 0; j < 2; j++)
                    wmma::mma_sync(c[i][j], a[i], bf[j], c[i][j]);
        }
    }
    __syncthreads();
    if (blockIdx.y == 0) ksbuf[tid] = kpart;
#pragma unroll
    for (int i = 0; i < 4; i++)
#pragma unroll
        for (int j = 0; j < 2; j++)
            wmma::store_matrix_sync(Cs + (wr * 64 + i * 16) * 132 + wc * 32 + j * 16,
                                    c[i][j], 132, wmma::mem_row_major);
    __syncthreads();

    __half* KV = g_KVh + (size_t)b * M * DV;
#pragma unroll
    for (int i = tid; i < 8192; i += 256) {
        int e = i * 2, r = e >> 7, cc = e & 127;
        __half2 h = __floats2half2_rn(Cs[r * 132 + cc], Cs[r * 132 + cc + 1]);
        *(__half2*)(KV + (size_t)(m0 + r) * DV + v0 + cc) = h;
    }
    if (blockIdx.y == 0 && tid < 128)
        g_Ksum[b * M + m0 + tid] = ksbuf[tid] + ksbuf[tid + 128];
}

// ---------------- GEMM2: out = (Qp @ KV) / norm (+ fused norm) ---------------
#define LDA2 72
#define SMEM2 69120  // As 18432, Bs 17408, Cs overlay 67584, ksm @67584, normbuf @68608

__global__ __launch_bounds__(256) void out_wmma_kernel(float* __restrict__ out) {
    extern __shared__ char smraw[];
    __half* As = (__half*)smraw;                    // [128][72] : [t][k]
    __half* Bs = (__half*)(smraw + 128 * LDA2 * 2); // [64][136] : [k][v]
    float*  Cs = (float*)smraw;                     // [128][132]
    float*  ksm = (float*)(smraw + 67584);          // [256]
    float*  normbuf = (float*)(smraw + 68608);      // [128]

    const int b  = blockIdx.z;
    const int t0 = blockIdx.x * 128, v0 = blockIdx.y * 128;
    const int tid = threadIdx.x, warp = tid >> 5;
    const int wr = warp & 1, wc = warp >> 1;

    ksm[tid] = g_Ksum[b * M + tid];   // 256 threads = 256 entries

    const __half* Qh = g_Qh  + ((size_t)b * NP + t0) * M;
    const __half* KV = g_KVh + (size_t)b * M * DV;

    wmma::fragment<wmma::accumulator, 16, 16, 16, float> c[4][2];
#pragma unroll
    for (int i = 0; i < 4; i++)
#pragma unroll
        for (int j = 0; j < 2; j++) wmma::fill_fragment(c[i][j], 0.f);

    float npart = 0.f;
    const int tnorm = tid >> 1, hf = tid & 1;
    for (int k0 = 0; k0 < M; k0 += 64) {
        __syncthreads();
#pragma unroll
        for (int i = tid; i < 1024; i += 256) {
            int r = i >> 3, q = i & 7;
            ((uint4*)(As + r * LDA2))[q] = ((const uint4*)(Qh + (size_t)r * M + k0))[q];
        }
#pragma unroll
        for (int i = tid; i < 1024; i += 256) {
            int t = i >> 4, q = i & 15;
            ((uint4*)(Bs + t * LDA1))[q] = ((const uint4*)(KV + (size_t)(k0 + t) * DV + v0))[q];
        }
        __syncthreads();
        {   // fused norm partial: npart += Qp[t, k0+hf*32 .. +32] . Ksum
            const __half2* qrow = (const __half2*)(As + tnorm * LDA2 + hf * 32);
            const float* kk = ksm + k0 + hf * 32;
#pragma unroll
            for (int mm = 0; mm < 16; mm++) {
                float2 q2 = __half22float2(qrow[mm]);
                npart += q2.x * kk[mm * 2] + q2.y * kk[mm * 2 + 1];
            }
        }
#pragma unroll
        for (int kk = 0; kk < 64; kk += 16) {
            wmma::fragment<wmma::matrix_a, 16, 16, 16, __half, wmma::row_major> a[4];
            wmma::fragment<wmma::matrix_b, 16, 16, 16, __half, wmma::row_major> bf[2];
#pragma unroll
            for (int i = 0; i < 4; i++)
                wmma::load_matrix_sync(a[i], As + (wr * 64 + i * 16) * LDA2 + kk, LDA2);
#pragma unroll
            for (int j = 0; j < 2; j++)
                wmma::load_matrix_sync(bf[j], Bs + kk * LDA1 + wc * 32 + j * 16, LDA1);
#pragma unroll
            for (int i = 0; i < 4; i++)
#pragma unroll
                for (int j = 0; j < 2; j++)
                    wmma::mma_sync(c[i][j], a[i], bf[j], c[i][j]);
        }
    }
    npart += __shfl_xor_sync(0xffffffffu, npart, 1);
    __syncthreads();
    if (hf == 0) normbuf[tnorm] = npart;
#pragma unroll
    for (int i = 0; i < 4; i++)
#pragma unroll
        for (int j = 0; j < 2; j++)
            wmma::store_matrix_sync(Cs + (wr * 64 + i * 16) * 132 + wc * 32 + j * 16,
                                    c[i][j], 132, wmma::mem_row_major);
    __syncthreads();

    float* op = out + ((size_t)b * NP + t0) * DV + v0;
#pragma unroll
    for (int i = tid; i < 8192; i += 256) {
        int e = i * 2, r = e >> 7, cc = e & 127;
        float inv = 1.0f / (normbuf[r] + EPS_NORM * (KSCALE * QSCALE));
        float2 v;
        v.x = Cs[r * 132 + cc]     * inv;
        v.y = Cs[r * 132 + cc + 1] * inv;
        *(float2*)(op + (size_t)r * DV + cc) = v;
    }
}

// ---------------- launch ------------------------------------------------------
extern "C" void kernel_launch(void* const* d_in, const int* in_sizes, int n_in,
                              void* d_out, int out_size) {
    const float* Q     = (const float*)d_in[0];
    const float* K     = (const float*)d_in[1];
    const float* V     = (const float*)d_in[2];
    const float* omega = (const float*)d_in[3];
    float* out = (float*)d_out;

    cudaFuncSetAttribute(phi_wmma_kernel, cudaFuncAttributeMaxDynamicSharedMemorySize, PHI_SMEM);
    cudaFuncSetAttribute(kv_wmma_kernel,  cudaFuncAttributeMaxDynamicSharedMemorySize, SMEM1);
    cudaFuncSetAttribute(out_wmma_kernel, cudaFuncAttributeMaxDynamicSharedMemorySize, SMEM2);

    init_kernel<<<1, 64>>>();
    omega_split_kernel<<<(D * M) / 256, 256>>>(omega);
    phi_wmma_kernel<<<2 * (N_TOK / 128), 512, PHI_SMEM>>>(Q, K);
    kv_wmma_kernel<<<dim3(2, 2, NB), 256, SMEM1>>>(V);
    out_wmma_kernel<<<dim3(4, 2, NB), 256, SMEM2>>>(out);
}

// round 6
// speedup vs baseline: 3.6485x; 1.0031x over previous
#include <cuda_runtime.h>
#include <cuda_fp16.h>
#include <mma.h>
#include <math.h>
#include <stdint.h>

using namespace nvcuda;

#define N_TOK 32768
#define NB 64
#define NP 512
#define D 128
#define M 256
#define DV 256
#define EPS_PHI 1e-4f
#define EPS_NORM 1e-8f
#define INV_SQRT_M 0.0625f
#define XSCALE 0.29730177875068026f   // 1/128^0.25
#define KSCALE 256.0f                 // anti-subnormal scale for Kp (cancels)
#define QSCALE 256.0f                 // anti-subnormal scale for Qp (cancels)
#define ESCALE 512.0f                 // storage scale for raw exp of K

// ---------------- scratch (static device globals) ---------------------------
__device__ float  g_segmax[NB];
__device__ float  g_bmax[N_TOK / 128];     // per-phi-block max (K side)
__device__ float  g_esum[(N_TOK / 128) * M]; // per-phi-block col sums of e
__device__ float  g_Ksum[NB * M];          // scaled, fp32
__device__ __align__(16) __half g_Qh [N_TOK * M];   // scaled phi(Q) [t][m]
__device__ __align__(16) __half g_Ke [N_TOK * M];   // exp(U-h-bmax)*ESCALE
__device__ __align__(16) __half g_KVh[NB * M * DV]; // scaled KV [b][m][v]
__device__ __align__(16) __half g_Whi[D * M];
__device__ __align__(16) __half g_Wlo[D * M];

// ---------------- helpers ----------------------------------------------------
__device__ __forceinline__ void atomicMaxF(float* addr, float val) {
    int* ia = (int*)addr;
    int old = *ia;
    while (__int_as_float(old) < val) {
        int assumed = old;
        old = atomicCAS(ia, assumed, __float_as_int(val));
        if (old == assumed) break;
    }
}

__device__ __forceinline__ void cp16(uint32_t dst, const void* src) {
    asm volatile("cp.async.cg.shared.global [%0], [%1], 16;" :: "r"(dst), "l"(src));
}

__global__ void init_kernel() {
    if (threadIdx.x < NB) g_segmax[threadIdx.x] = -INFINITY;
}

__global__ void omega_split_kernel(const float* __restrict__ omega) {
    int i = blockIdx.x * 256 + threadIdx.x;
    float w = omega[i];
    __half hi = __float2half_rn(w);
    g_Whi[i] = hi;
    g_Wlo[i] = __float2half_rn(w - __half2float(hi));
}

// Ksum[b][m] = (sum_cb exp(bmax-segmax)*esum + NP*EPS*ESCALE) scaled
__global__ void ksum_kernel() {
    const int b = blockIdx.x, m = threadIdx.x;
    const float sgm = g_segmax[b];
    float s = 0.f;
#pragma unroll
    for (int cb = 0; cb < 4; cb++)
        s += __expf(g_bmax[b * 4 + cb] - sgm) * g_esum[(b * 4 + cb) * M + m];
    g_Ksum[b * M + m] = (s * (1.f / ESCALE) + NP * EPS_PHI) * (INV_SQRT_M * KSCALE);
}

// ---------------- phi via split-fp16 wmma ------------------------------------
#define PHI_LDA 136
#define PHI_LDB 264
#define PHI_LDC 260
#define PHI_SMEM 209920

__global__ __launch_bounds__(512, 1) void phi_wmma_kernel(
    const float* __restrict__ Q, const float* __restrict__ K) {
    extern __shared__ char smraw[];
    __half* Ahi = (__half*)smraw;
    __half* Alo = (__half*)(smraw + 34816);
    __half* Bhi = (__half*)(smraw + 69632);
    __half* Blo = (__half*)(smraw + 137216);
    float*  Cs  = (float*)smraw;
    float*  hsm = (float*)(smraw + 204800);
    float*  mxs = (float*)(smraw + 205312);
    float2* esb = (float2*)(smraw + 205824);   // [512]

    const int tid  = threadIdx.x;
    const int warp = tid >> 5, lane = tid & 31;
    const bool isq = blockIdx.x < (N_TOK / 128);
    const int tile = isq ? blockIdx.x : blockIdx.x - (N_TOK / 128);
    const int row0 = tile * 128;
    const float* X = isq ? Q : K;

    {
        int r = tid >> 2, j = tid & 3;
        const float4* src = (const float4*)(X + (size_t)(row0 + r) * D + j * 32);
        __half* ah = Ahi + r * PHI_LDA + j * 32;
        __half* al = Alo + r * PHI_LDA + j * 32;
        float ss = 0.f;
#pragma unroll
        for (int q = 0; q < 8; q++) {
            float4 v = src[q];
            v.x *= XSCALE; v.y *= XSCALE; v.z *= XSCALE; v.w *= XSCALE;
            ss += v.x * v.x + v.y * v.y + v.z * v.z + v.w * v.w;
            __half hx = __float2half_rn(v.x), hy = __float2half_rn(v.y);
            __half hz = __float2half_rn(v.z), hw = __float2half_rn(v.w);
            ((__half2*)(ah + q * 4))[0] = __halves2half2(hx, hy);
            ((__half2*)(ah + q * 4))[1] = __halves2half2(hz, hw);
            ((__half2*)(al + q * 4))[0] = __floats2half2_rn(v.x - __half2float(hx),
                                                            v.y - __half2float(hy));
            ((__half2*)(al + q * 4))[1] = __floats2half2_rn(v.z - __half2float(hz),
                                                            v.w - __half2float(hw));
        }
        ss += __shfl_xor_sync(0xffffffffu, ss, 1);
        ss += __shfl_xor_sync(0xffffffffu, ss, 2);
        if (j == 0) hsm[r] = 0.5f * ss;
    }
#pragma unroll
    for (int it = 0; it < 16; it++) {
        int i = it * 512 + tid;
        int sel = i >> 12;
        int j = i & 4095;
        int rr = j >> 5, c8 = j & 31;
        uint4 v = sel ? ((const uint4*)g_Wlo)[j] : ((const uint4*)g_Whi)[j];
        *(uint4*)((sel ? Blo : Bhi) + rr * PHI_LDB + c8 * 8) = v;
    }
    __syncthreads();

    const int wr = warp >> 2, wc = warp & 3;
    wmma::fragment<wmma::accumulator, 16, 16, 16, float> c[2][4];
#pragma unroll
    for (int i = 0; i < 2; i++)
#pragma unroll
        for (int j = 0; j < 4; j++) wmma::fill_fragment(c[i][j], 0.f);

#pragma unroll
    for (int ks = 0; ks < 8; ks++) {
        int kk = ks * 16;
        wmma::fragment<wmma::matrix_a, 16, 16, 16, __half, wmma::row_major> ah[2], al[2];
        wmma::fragment<wmma::matrix_b, 16, 16, 16, __half, wmma::row_major> bh[4], bl[4];
#pragma unroll
        for (int i = 0; i < 2; i++) {
            wmma::load_matrix_sync(ah[i], Ahi + (wr * 32 + i * 16) * PHI_LDA + kk, PHI_LDA);
            wmma::load_matrix_sync(al[i], Alo + (wr * 32 + i * 16) * PHI_LDA + kk, PHI_LDA);
        }
#pragma unroll
        for (int j = 0; j < 4; j++) {
            wmma::load_matrix_sync(bh[j], Bhi + kk * PHI_LDB + wc * 64 + j * 16, PHI_LDB);
            wmma::load_matrix_sync(bl[j], Blo + kk * PHI_LDB + wc * 64 + j * 16, PHI_LDB);
        }
#pragma unroll
        for (int i = 0; i < 2; i++)
#pragma unroll
            for (int j = 0; j < 4; j++) {
                wmma::mma_sync(c[i][j], ah[i], bh[j], c[i][j]);
                wmma::mma_sync(c[i][j], al[i], bh[j], c[i][j]);
                wmma::mma_sync(c[i][j], ah[i], bl[j], c[i][j]);
            }
    }
    __syncthreads();

    if (isq) {
#pragma unroll
        for (int i = 0; i < 2; i++)
#pragma unroll
            for (int j = 0; j < 4; j++)
                wmma::store_matrix_sync(Cs + (wr * 32 + i * 16) * PHI_LDC + wc * 64 + j * 16,
                                        c[i][j], PHI_LDC, wmma::mem_row_major);
        __syncthreads();
#pragma unroll
        for (int rr = 0; rr < 8; rr++) {
            int row = warp * 8 + rr;
            float mx = -INFINITY;
#pragma unroll
            for (int cc = lane; cc < M; cc += 32) mx = fmaxf(mx, Cs[row * PHI_LDC + cc]);
#pragma unroll
            for (int o = 16; o > 0; o >>= 1) mx = fmaxf(mx, __shfl_xor_sync(0xffffffffu, mx, o));
            if (lane == 0) mxs[row] = mx;
        }
        __syncthreads();
#pragma unroll
        for (int it = 0; it < 32; it++) {
            int i = it * 512 + tid;
            int row = i >> 7, c2 = i & 127;
            float hm = hsm[row] + mxs[row];
            float2 u = *(const float2*)&Cs[row * PHI_LDC + c2 * 2];
            float a = (__expf(u.x - hm) + EPS_PHI) * (INV_SQRT_M * QSCALE);
            float b = (__expf(u.y - hm) + EPS_PHI) * (INV_SQRT_M * QSCALE);
            ((__half2*)g_Qh)[(size_t)(row0 + row) * (M / 2) + c2] = __floats2half2_rn(a, b);
        }
    } else {
        float bm = -INFINITY;
#pragma unroll
        for (int i = 0; i < 2; i++)
#pragma unroll
            for (int j = 0; j < 4; j++)
#pragma unroll
                for (int e = 0; e < c[i][j].num_elements; e++)
                    bm = fmaxf(bm, c[i][j].x[e]);
#pragma unroll
        for (int o = 16; o > 0; o >>= 1) bm = fmaxf(bm, __shfl_xor_sync(0xffffffffu, bm, o));
        if (lane == 0) mxs[warp] = bm;
        __syncthreads();
#pragma unroll
        for (int i = 0; i < 2; i++)
#pragma unroll
            for (int j = 0; j < 4; j++)
                wmma::store_matrix_sync(Cs + (wr * 32 + i * 16) * PHI_LDC + wc * 64 + j * 16,
                                        c[i][j], PHI_LDC, wmma::mem_row_major);
        float bmax = mxs[0];
#pragma unroll
        for (int w = 1; w < 16; w++) bmax = fmaxf(bmax, mxs[w]);
        __syncthreads();
        float2 es = make_float2(0.f, 0.f);   // fixed half2-column per thread
#pragma unroll
        for (int it = 0; it < 32; it++) {
            int i = it * 512 + tid;
            int row = i >> 7, c2 = i & 127;
            float hm = hsm[row] + bmax;
            float2 u = *(const float2*)&Cs[row * PHI_LDC + c2 * 2];
            float a = __expf(u.x - hm) * ESCALE;
            float b = __expf(u.y - hm) * ESCALE;
            es.x += a; es.y += b;
            ((__half2*)g_Ke)[(size_t)(row0 + row) * (M / 2) + c2] = __floats2half2_rn(a, b);
        }
        esb[tid] = es;
        __syncthreads();
        if (tid < 128) {
            float2 t0 = esb[tid], t1 = esb[tid + 128];
            float2 t2 = esb[tid + 256], t3 = esb[tid + 384];
            g_esum[tile * M + tid * 2]     = t0.x + t1.x + t2.x + t3.x;
            g_esum[tile * M + tid * 2 + 1] = t0.y + t1.y + t2.y + t3.y;
        }
        if (tid == 0) {
            g_bmax[tile] = bmax;
            atomicMaxF(&g_segmax[tile >> 2], bmax);
        }
    }
}

// ---------------- GEMM1: KV[b] = Kp^T @ V  (register-pipelined) --------------
#define LDA1 136
#define G1_STAGE 34816
#define SMEM1 69632

struct G1Regs { uint4 rA[4]; float4 rB[8]; };

__device__ __forceinline__ void g1_load(G1Regs& rg, const __half* Ke,
                                        const float* Vb, int k0, int m0, int v0,
                                        int tid) {
#pragma unroll
    for (int u = 0; u < 4; u++) {
        int i = tid + u * 256, t = i >> 4, q = i & 15;
        rg.rA[u] = ((const uint4*)(Ke + (size_t)(k0 + t) * M + m0))[q];
    }
#pragma unroll
    for (int u = 0; u < 8; u++) {
        int i = tid + u * 256, t = i >> 5, q = i & 31;
        rg.rB[u] = ((const float4*)(Vb + (size_t)(k0 + t) * DV + v0))[q];
    }
}

__device__ __forceinline__ void g1_store(const G1Regs& rg, char* smraw, int s,
                                         __half2 c1, __half2 c2h, int tid) {
    __half* As = (__half*)(smraw + s * G1_STAGE);
    __half* Bs = As + 64 * LDA1;
#pragma unroll
    for (int u = 0; u < 4; u++) {
        int i = tid + u * 256, t = i >> 4, q = i & 15;
        uint4 raw = rg.rA[u];
        __half2* pr = (__half2*)&raw;
        pr[0] = __hfma2(pr[0], c1, c2h);
        pr[1] = __hfma2(pr[1], c1, c2h);
        pr[2] = __hfma2(pr[2], c1, c2h);
        pr[3] = __hfma2(pr[3], c1, c2h);
        ((uint4*)(As + t * LDA1))[q] = raw;
    }
#pragma unroll
    for (int u = 0; u < 8; u++) {
        int i = tid + u * 256, t = i >> 5, q = i & 31;
        float4 f = rg.rB[u];
        ((__half2*)(Bs + t * LDA1))[q * 2]     = __floats2half2_rn(f.x, f.y);
        ((__half2*)(Bs + t * LDA1))[q * 2 + 1] = __floats2half2_rn(f.z, f.w);
    }
}

__global__ __launch_bounds__(256) void kv_wmma_kernel(const float* __restrict__ V) {
    extern __shared__ char smraw[];
    float* Cs = (float*)smraw;

    const int b  = blockIdx.z;
    const int m0 = blockIdx.x * 128, v0 = blockIdx.y * 128;
    const int tid = threadIdx.x, warp = tid >> 5;
    const int wr = warp & 1, wc = warp >> 1;

    const float sgm = g_segmax[b];
    __half2 c1h[4];
#pragma unroll
    for (int cb = 0; cb < 4; cb++) {
        float corr = __expf(g_bmax[b * 4 + cb] - sgm) * (INV_SQRT_M * KSCALE / ESCALE);
        c1h[cb] = __float2half2_rn(corr);
    }
    const __half2 c2h = __float2half2_rn(EPS_PHI * INV_SQRT_M * KSCALE);

    const __half* Ke = g_Ke + (size_t)b * NP * M;
    const float*  Vb = V    + (size_t)b * NP * DV;

    wmma::fragment<wmma::accumulator, 16, 16, 16, float> c[4][2];
#pragma unroll
    for (int i = 0; i < 4; i++)
#pragma unroll
        for (int j = 0; j < 2; j++) wmma::fill_fragment(c[i][j], 0.f);

    G1Regs rg;
    g1_load(rg, Ke, Vb, 0, m0, v0, tid);
    g1_store(rg, smraw, 0, c1h[0], c2h, tid);

    for (int ch = 0; ch < 8; ch++) {
        int s = ch & 1;
        __syncthreads();                           // stage s ready
        if (ch < 7) g1_load(rg, Ke, Vb, (ch + 1) * 64, m0, v0, tid);  // in flight

        const __half* As = (const __half*)(smraw + s * G1_STAGE);
        const __half* Bs = As + 64 * LDA1;
#pragma unroll
        for (int kk = 0; kk < 64; kk += 16) {
            wmma::fragment<wmma::matrix_a, 16, 16, 16, __half, wmma::col_major> a[4];
            wmma::fragment<wmma::matrix_b, 16, 16, 16, __half, wmma::row_major> bf[2];
#pragma unroll
            for (int i = 0; i < 4; i++)
                wmma::load_matrix_sync(a[i], As + kk * LDA1 + wr * 64 + i * 16, LDA1);
#pragma unroll
            for (int j = 0; j < 2; j++)
                wmma::load_matrix_sync(bf[j], Bs + kk * LDA1 + wc * 32 + j * 16, LDA1);
#pragma unroll
            for (int i = 0; i < 4; i++)
#pragma unroll
                for (int j = 0; j < 2; j++)
                    wmma::mma_sync(c[i][j], a[i], bf[j], c[i][j]);
        }
        __syncthreads();                           // all reads of s^1 done
        if (ch < 7) g1_store(rg, smraw, s ^ 1, c1h[(ch + 1) >> 1], c2h, tid);
    }

#pragma unroll
    for (int i = 0; i < 4; i++)
#pragma unroll
        for (int j = 0; j < 2; j++)
            wmma::store_matrix_sync(Cs + (wr * 64 + i * 16) * 132 + wc * 32 + j * 16,
                                    c[i][j], 132, wmma::mem_row_major);
    __syncthreads();

    __half* KV = g_KVh + (size_t)b * M * DV;
#pragma unroll
    for (int i = tid; i < 8192; i += 256) {
        int e = i * 2, r = e >> 7, cc = e & 127;
        __half2 h = __floats2half2_rn(Cs[r * 132 + cc], Cs[r * 132 + cc + 1]);
        *(__half2*)(KV + (size_t)(m0 + r) * DV + v0 + cc) = h;
    }
}

// ---------------- GEMM2: out = (Qp @ KV) / norm  (cp.async pipelined) --------
#define LDA2 72
#define G2_STAGE 35840   // As 18432 + Bs 17408
#define SMEM2 73216      // 2 stages + ksm(1024) + normbuf(512)

__global__ __launch_bounds__(256) void out_wmma_kernel(float* __restrict__ out) {
    extern __shared__ char smraw[];
    float* Cs      = (float*)smraw;
    float* ksm     = (float*)(smraw + 71680);
    float* normbuf = (float*)(smraw + 72704);
    const uint32_t sbase = (uint32_t)__cvta_generic_to_shared(smraw);

    const int b  = blockIdx.z;
    const int t0 = blockIdx.x * 128, v0 = blockIdx.y * 128;
    const int tid = threadIdx.x, warp = tid >> 5;
    const int wr = warp & 1, wc = warp >> 1;

    ksm[tid] = g_Ksum[b * M + tid];

    const __half* Qh = g_Qh  + ((size_t)b * NP + t0) * M;
    const __half* KV = g_KVh + (size_t)b * M * DV;

    // async copy of chunk k0 into stage s
    auto copy_stage = [&](int s, int k0) {
        uint32_t abase = sbase + s * G2_STAGE;
        uint32_t bbase = abase + 18432;
#pragma unroll
        for (int u = 0; u < 4; u++) {
            int i = tid + u * 256, r = i >> 3, q = i & 7;
            cp16(abase + (r * LDA2 + q * 8) * 2, Qh + (size_t)r * M + k0 + q * 8);
        }
#pragma unroll
        for (int u = 0; u < 4; u++) {
            int i = tid + u * 256, t = i >> 4, q = i & 15;
            cp16(bbase + (t * LDA1 + q * 8) * 2, KV + (size_t)(k0 + t) * DV + v0 + q * 8);
        }
        asm volatile("cp.async.commit_group;");
    };

    wmma::fragment<wmma::accumulator, 16, 16, 16, float> c[4][2];
#pragma unroll
    for (int i = 0; i < 4; i++)
#pragma unroll
        for (int j = 0; j < 2; j++) wmma::fill_fragment(c[i][j], 0.f);

    copy_stage(0, 0);
    copy_stage(1, 64);

    float npart = 0.f;
    const int tnorm = tid >> 1, hf = tid & 1;
    for (int ch = 0; ch < 4; ch++) {
        int s = ch & 1;
        if (ch < 3) asm volatile("cp.async.wait_group 1;");
        else        asm volatile("cp.async.wait_group 0;");
        __syncthreads();

        const __half* As = (const __half*)(smraw + s * G2_STAGE);
        const __half* Bs = As + 18432 / 2;
        {   // fused norm partial
            const __half2* qrow = (const __half2*)(As + tnorm * LDA2 + hf * 32);
            const float* kk2 = ksm + ch * 64 + hf * 32;
#pragma unroll
            for (int mm = 0; mm < 16; mm++) {
                float2 q2 = __half22float2(qrow[mm]);
                npart += q2.x * kk2[mm * 2] + q2.y * kk2[mm * 2 + 1];
            }
        }
#pragma unroll
        for (int kk = 0; kk < 64; kk += 16) {
            wmma::fragment<wmma::matrix_a, 16, 16, 16, __half, wmma::row_major> a[4];
            wmma::fragment<wmma::matrix_b, 16, 16, 16, __half, wmma::row_major> bf[2];
#pragma unroll
            for (int i = 0; i < 4; i++)
                wmma::load_matrix_sync(a[i], As + (wr * 64 + i * 16) * LDA2 + kk, LDA2);
#pragma unroll
            for (int j = 0; j < 2; j++)
                wmma::load_matrix_sync(bf[j], Bs + kk * LDA1 + wc * 32 + j * 16, LDA1);
#pragma unroll
            for (int i = 0; i < 4; i++)
#pragma unroll
                for (int j = 0; j < 2; j++)
                    wmma::mma_sync(c[i][j], a[i], bf[j], c[i][j]);
        }
        __syncthreads();                    // stage s fully read
        if (ch < 2) copy_stage(s, (ch + 2) * 64);
    }

    npart += __shfl_xor_sync(0xffffffffu, npart, 1);
    if (hf == 0) normbuf[tnorm] = npart;
#pragma unroll
    for (int i = 0; i < 4; i++)
#pragma unroll
        for (int j = 0; j < 2; j++)
            wmma::store_matrix_sync(Cs + (wr * 64 + i * 16) * 132 + wc * 32 + j * 16,
                                    c[i][j], 132, wmma::mem_row_major);
    __syncthreads();

    float* op = out + ((size_t)b * NP + t0) * DV + v0;
#pragma unroll
    for (int i = tid; i < 8192; i += 256) {
        int e = i * 2, r = e >> 7, cc = e & 127;
        float inv = 1.0f / (normbuf[r] + EPS_NORM * (KSCALE * QSCALE));
        float2 v;
        v.x = Cs[r * 132 + cc]     * inv;
        v.y = Cs[r * 132 + cc + 1] * inv;
        *(float2*)(op + (size_t)r * DV + cc) = v;
    }
}

// ---------------- launch ------------------------------------------------------
extern "C" void kernel_launch(void* const* d_in, const int* in_sizes, int n_in,
                              void* d_out, int out_size) {
    const float* Q     = (const float*)d_in[0];
    const float* K     = (const float*)d_in[1];
    const float* V     = (const float*)d_in[2];
    const float* omega = (const float*)d_in[3];
    float* out = (float*)d_out;

    cudaFuncSetAttribute(phi_wmma_kernel, cudaFuncAttributeMaxDynamicSharedMemorySize, PHI_SMEM);
    cudaFuncSetAttribute(kv_wmma_kernel,  cudaFuncAttributeMaxDynamicSharedMemorySize, SMEM1);
    cudaFuncSetAttribute(out_wmma_kernel, cudaFuncAttributeMaxDynamicSharedMemorySize, SMEM2);

    init_kernel<<<1, 64>>>();
    omega_split_kernel<<<(D * M) / 256, 256>>>(omega);
    phi_wmma_kernel<<<2 * (N_TOK / 128), 512, PHI_SMEM>>>(Q, K);
    ksum_kernel<<<NB, 256>>>();
    kv_wmma_kernel<<<dim3(2, 2, NB), 256, SMEM1>>>(V);
    out_wmma_kernel<<<dim3(4, 2, NB), 256, SMEM2>>>(out);
}